// round 5
// baseline (speedup 1.0000x reference)
#include <cuda_runtime.h>
#include <cstdint>

// Problem constants (B=4, L=2048, H=16, D=64 — fixed by the dataset)
#define Bc 4
#define Hc 16
#define Lc 2048
#define Dc 64
#define BM 256
#define BN 64
#define NT 256
#define NW 8

// Smem strides:
//   K/V tiles: uint2[64][KSu], KSu=68 (hi,lo tf32 pairs, one LDS.64 per element)
//   P tiles  : float[32][PSf] per warp, PSf=72
#define KSu 68
#define PSf 72
#define SMEM_BYTES (2 * 64 * KSu * 8 + NW * 32 * PSf * 4)   // 143,360 B

__device__ __forceinline__ void tf32_split(float x, uint32_t& hi, uint32_t& lo) {
    uint32_t h;
    asm("cvt.rna.tf32.f32 %0, %1;" : "=r"(h) : "f"(x));
    hi = h;
    float lf = x - __uint_as_float(h);
    asm("cvt.rna.tf32.f32 %0, %1;" : "=r"(lo) : "f"(lf));
}
__device__ __forceinline__ uint32_t tf32_rna(float x) {
    uint32_t h;
    asm("cvt.rna.tf32.f32 %0, %1;" : "=r"(h) : "f"(x));
    return h;
}
__device__ __forceinline__ void mma8(float* d,
                                     uint32_t a0, uint32_t a1, uint32_t a2, uint32_t a3,
                                     uint32_t b0, uint32_t b1) {
    asm("mma.sync.aligned.m16n8k8.row.col.f32.tf32.tf32.f32 "
        "{%0,%1,%2,%3},{%4,%5,%6,%7},{%8,%9},{%0,%1,%2,%3};"
        : "+f"(d[0]), "+f"(d[1]), "+f"(d[2]), "+f"(d[3])
        : "r"(a0), "r"(a1), "r"(a2), "r"(a3), "r"(b0), "r"(b1));
}

__global__ void __launch_bounds__(NT)
logsparse_flash_tc5_kernel(const float* __restrict__ Q,
                           const float* __restrict__ K,
                           const float* __restrict__ V,
                           float* __restrict__ O) {
    extern __shared__ char smc[];
    uint2* KH = (uint2*)smc;                 // [64 key][KSu d]  (hi,lo)
    uint2* VH = KH + 64 * KSu;               // [64 key][KSu d]  (hi,lo)
    float* Pa = (float*)(VH + 64 * KSu);     // NW x [32][PSf]

    // Heavy blocks (large m) first: flatten triangular imbalance.
    const int m  = (int)gridDim.x - 1 - (int)blockIdx.x;
    const int bh = blockIdx.y;
    const int b  = bh >> 4;
    const int h  = bh & 15;

    const int tid  = threadIdx.x;
    const int wid  = tid >> 5;
    const int lane = tid & 31;
    const int g    = lane >> 2;
    const int tg   = lane & 3;

    float* Pw = Pa + wid * (32 * PSf);
    const int R0 = wid * 32;                 // warp's 32 rows within tile

    const size_t rs = (size_t)Hc * Dc;       // 1024 floats between seq positions
    const float* Qg = Q + ((size_t)b * Lc + (size_t)m * BM) * rs + (size_t)h * Dc;
    const float* Kg = K + (size_t)b * Lc * rs + (size_t)h * Dc;
    const float* Vg = V + (size_t)b * Lc * rs + (size_t)h * Dc;

    // ---- Load Q fragments once, pre-scaled by log2(e) (exp -> exp2) ----
    const float LOG2E = 1.4426950408889634f;
    float qf[2][8][4];
#pragma unroll
    for (int t = 0; t < 2; ++t)
#pragma unroll
        for (int cc = 0; cc < 8; ++cc) {
            int k0 = 8 * cc + tg;
            int rA = R0 + 16 * t + g, rB = rA + 8;
            qf[t][cc][0] = Qg[(size_t)rA * rs + k0]     * LOG2E;
            qf[t][cc][1] = Qg[(size_t)rB * rs + k0]     * LOG2E;
            qf[t][cc][2] = Qg[(size_t)rA * rs + k0 + 4] * LOG2E;
            qf[t][cc][3] = Qg[(size_t)rB * rs + k0 + 4] * LOG2E;
        }

    // ---- State (log2-domain) + O accumulators ----
    float o[2][8][4];
    float mrA[2] = {-1e30f, -1e30f}, mrB[2] = {-1e30f, -1e30f};
    float lA[2] = {0.f, 0.f}, lB[2] = {0.f, 0.f};
#pragma unroll
    for (int t = 0; t < 2; ++t)
#pragma unroll
        for (int j = 0; j < 8; ++j)
            o[t][j][0] = o[t][j][1] = o[t][j][2] = o[t][j][3] = 0.f;

    const int wRowMax = m * BM + R0 + 31;    // warp's last global row
    const int nend = (m * BM + BM - 1) / BN; // 4m+3

    for (int n = 0; n <= nend; ++n) {
        __syncthreads();
        // ---- Load K,V tile; split to tf32 hi/lo once ----
        const int nBase = n * BN;
#pragma unroll
        for (int it = 0; it < 4; ++it) {
            int idx = tid + it * NT;       // 0..1023
            int r = idx >> 4, c4 = idx & 15;
            const size_t go = (size_t)(nBase + r) * rs + c4 * 4;
            float4 kv = *(const float4*)(Kg + go);
            float4 vv = *(const float4*)(Vg + go);
            uint2* kd = KH + r * KSu + c4 * 4;
            uint2* vd = VH + r * KSu + c4 * 4;
            uint32_t hi, lo;
            tf32_split(kv.x, hi, lo); kd[0] = make_uint2(hi, lo);
            tf32_split(kv.y, hi, lo); kd[1] = make_uint2(hi, lo);
            tf32_split(kv.z, hi, lo); kd[2] = make_uint2(hi, lo);
            tf32_split(kv.w, hi, lo); kd[3] = make_uint2(hi, lo);
            tf32_split(vv.x, hi, lo); vd[0] = make_uint2(hi, lo);
            tf32_split(vv.y, hi, lo); vd[1] = make_uint2(hi, lo);
            tf32_split(vv.z, hi, lo); vd[2] = make_uint2(hi, lo);
            tf32_split(vv.w, hi, lo); vd[3] = make_uint2(hi, lo);
        }
        __syncthreads();

        if (nBase > wRowMax) continue;     // warp fully masked for this block

        // ---- Per m16-tile: S = QK^T (3xTF32), softmax, stage tf32 P ----
#pragma unroll
        for (int t = 0; t < 2; ++t) {
            const int gA = m * BM + R0 + 16 * t + g;
            const int gB = gA + 8;

            float s[8][4];
#pragma unroll
            for (int j = 0; j < 8; ++j) { s[j][0] = s[j][1] = s[j][2] = s[j][3] = 0.f; }

#pragma unroll
            for (int cc = 0; cc < 8; ++cc) {
                uint32_t qh[4], ql[4];
#pragma unroll
                for (int e = 0; e < 4; ++e) tf32_split(qf[t][cc][e], qh[e], ql[e]);
#pragma unroll
                for (int j = 0; j < 8; ++j) {
                    // S B-frag: Kt[k=d][n=key] => K[key=8j+g][d=8cc+tg(+4)]
                    uint2 k0 = KH[(8 * j + g) * KSu + 8 * cc + tg];
                    uint2 k1 = KH[(8 * j + g) * KSu + 8 * cc + tg + 4];
                    mma8(s[j], qh[0], qh[1], qh[2], qh[3], k0.x, k1.x);
                    mma8(s[j], ql[0], ql[1], ql[2], ql[3], k0.x, k1.x);
                    mma8(s[j], qh[0], qh[1], qh[2], qh[3], k0.y, k1.y);
                }
            }

            // Causal mask (log2 domain; only when block touches diagonal)
            if (nBase + BN - 1 > gA) {
#pragma unroll
                for (int j = 0; j < 8; ++j) {
                    int c0 = nBase + 8 * j + 2 * tg;
                    if (c0     > gA) s[j][0] = -1e30f;
                    if (c0 + 1 > gA) s[j][1] = -1e30f;
                    if (c0     > gB) s[j][2] = -1e30f;
                    if (c0 + 1 > gB) s[j][3] = -1e30f;
                }
            }

            // Online softmax over 4-lane row groups
            float tA = s[0][0], tB = s[0][2];
#pragma unroll
            for (int j = 0; j < 8; ++j) {
                tA = fmaxf(tA, fmaxf(s[j][0], s[j][1]));
                tB = fmaxf(tB, fmaxf(s[j][2], s[j][3]));
            }
            tA = fmaxf(tA, __shfl_xor_sync(0xffffffffu, tA, 1));
            tA = fmaxf(tA, __shfl_xor_sync(0xffffffffu, tA, 2));
            tB = fmaxf(tB, __shfl_xor_sync(0xffffffffu, tB, 1));
            tB = fmaxf(tB, __shfl_xor_sync(0xffffffffu, tB, 2));
            float mnA = fmaxf(mrA[t], tA), mnB = fmaxf(mrB[t], tB);
            float scA = exp2f(mrA[t] - mnA), scB = exp2f(mrB[t] - mnB);
            float rsA = 0.f, rsB = 0.f;
#pragma unroll
            for (int j = 0; j < 8; ++j) {
                // exp2, then round to tf32 ONCE; the rounded value feeds both
                // the row-sum and the PV mma, so normalization is consistent.
                uint32_t p0 = tf32_rna(exp2f(s[j][0] - mnA));
                uint32_t p1 = tf32_rna(exp2f(s[j][1] - mnA));
                uint32_t p2 = tf32_rna(exp2f(s[j][2] - mnB));
                uint32_t p3 = tf32_rna(exp2f(s[j][3] - mnB));
                rsA += __uint_as_float(p0) + __uint_as_float(p1);
                rsB += __uint_as_float(p2) + __uint_as_float(p3);
                int c = 8 * j + 2 * tg;
                *(float2*)(Pw + (16 * t + g)     * PSf + c) =
                    make_float2(__uint_as_float(p0), __uint_as_float(p1));
                *(float2*)(Pw + (16 * t + g + 8) * PSf + c) =
                    make_float2(__uint_as_float(p2), __uint_as_float(p3));
            }
            rsA += __shfl_xor_sync(0xffffffffu, rsA, 1);
            rsA += __shfl_xor_sync(0xffffffffu, rsA, 2);
            rsB += __shfl_xor_sync(0xffffffffu, rsB, 1);
            rsB += __shfl_xor_sync(0xffffffffu, rsB, 2);
            lA[t] = lA[t] * scA + rsA;  mrA[t] = mnA;
            lB[t] = lB[t] * scB + rsB;  mrB[t] = mnB;
#pragma unroll
            for (int j = 0; j < 8; ++j) {
                o[t][j][0] *= scA; o[t][j][1] *= scA;
                o[t][j][2] *= scB; o[t][j][3] *= scB;
            }
        }
        __syncwarp();

        // ---- O += P V : 2 mma terms (P exact tf32, V hi+lo), tiles share V ----
#pragma unroll
        for (int cc = 0; cc < 8; ++cc) {
            uint32_t a0[4], a1[4];
            a0[0] = __float_as_uint(Pw[(g)      * PSf + 8 * cc + tg]);
            a0[1] = __float_as_uint(Pw[(g + 8)  * PSf + 8 * cc + tg]);
            a0[2] = __float_as_uint(Pw[(g)      * PSf + 8 * cc + tg + 4]);
            a0[3] = __float_as_uint(Pw[(g + 8)  * PSf + 8 * cc + tg + 4]);
            a1[0] = __float_as_uint(Pw[(g + 16) * PSf + 8 * cc + tg]);
            a1[1] = __float_as_uint(Pw[(g + 24) * PSf + 8 * cc + tg]);
            a1[2] = __float_as_uint(Pw[(g + 16) * PSf + 8 * cc + tg + 4]);
            a1[3] = __float_as_uint(Pw[(g + 24) * PSf + 8 * cc + tg + 4]);
#pragma unroll
            for (int j = 0; j < 8; ++j) {
                // PV B-frag: B[k=key][n=d] => V[key=8cc+tg(+4)][d=8j+g]
                uint2 v0 = VH[(8 * cc + tg)     * KSu + 8 * j + g];
                uint2 v1 = VH[(8 * cc + tg + 4) * KSu + 8 * j + g];
                mma8(o[0][j], a0[0], a0[1], a0[2], a0[3], v0.x, v1.x);
                mma8(o[0][j], a0[0], a0[1], a0[2], a0[3], v0.y, v1.y);
                mma8(o[1][j], a1[0], a1[1], a1[2], a1[3], v0.x, v1.x);
                mma8(o[1][j], a1[0], a1[1], a1[2], a1[3], v0.y, v1.y);
            }
        }
    }

    // ---- Epilogue: normalize, store (output [B, H, L, D]) ----
    float* Og = O + ((size_t)(b * Hc + h) * Lc + (size_t)m * BM) * Dc;
#pragma unroll
    for (int t = 0; t < 2; ++t) {
        float invA = 1.f / lA[t], invB = 1.f / lB[t];
        size_t rA = (size_t)(R0 + 16 * t + g), rB = rA + 8;
#pragma unroll
        for (int j = 0; j < 8; ++j) {
            int c = 8 * j + 2 * tg;
            *(float2*)(Og + rA * Dc + c) = make_float2(o[t][j][0] * invA, o[t][j][1] * invA);
            *(float2*)(Og + rB * Dc + c) = make_float2(o[t][j][2] * invB, o[t][j][3] * invB);
        }
    }
}

extern "C" void kernel_launch(void* const* d_in, const int* in_sizes, int n_in,
                              void* d_out, int out_size) {
    const float* Q = (const float*)d_in[0];
    const float* K = (const float*)d_in[1];
    const float* V = (const float*)d_in[2];
    float* O = (float*)d_out;

    cudaFuncSetAttribute(logsparse_flash_tc5_kernel,
                         cudaFuncAttributeMaxDynamicSharedMemorySize, SMEM_BYTES);

    dim3 grid(Lc / BM, Bc * Hc);
    logsparse_flash_tc5_kernel<<<grid, NT, SMEM_BYTES>>>(Q, K, V, O);
}

// round 7
// speedup vs baseline: 1.3754x; 1.3754x over previous
#include <cuda_runtime.h>
#include <cstdint>

// Problem constants (B=4, L=2048, H=16, D=64 — fixed by the dataset)
#define Bc 4
#define Hc 16
#define Lc 2048
#define Dc 64
#define BM 128
#define BN 64
#define NT 256
#define NW 8

// Smem:
//   KH/VH : uint2[64 key][KSu d]  (tf32 hi,lo pairs; one LDS.64 per element)
//   P     : per-warp float[16][PSf]
#define KSu 68
#define PSf 68
#define SMEM_BYTES (2 * 64 * KSu * 8 + NW * 16 * PSf * 4)   // 104,448 B -> 2 CTAs/SM

__device__ __forceinline__ void tf32_split(float x, uint32_t& hi, uint32_t& lo) {
    uint32_t h;
    asm("cvt.rna.tf32.f32 %0, %1;" : "=r"(h) : "f"(x));
    hi = h;
    float lf = x - __uint_as_float(h);
    asm("cvt.rna.tf32.f32 %0, %1;" : "=r"(lo) : "f"(lf));
}
__device__ __forceinline__ uint32_t tf32_rna(float x) {
    uint32_t h;
    asm("cvt.rna.tf32.f32 %0, %1;" : "=r"(h) : "f"(x));
    return h;
}
__device__ __forceinline__ void mma8(float* d,
                                     uint32_t a0, uint32_t a1, uint32_t a2, uint32_t a3,
                                     uint32_t b0, uint32_t b1) {
    asm("mma.sync.aligned.m16n8k8.row.col.f32.tf32.tf32.f32 "
        "{%0,%1,%2,%3},{%4,%5,%6,%7},{%8,%9},{%0,%1,%2,%3};"
        : "+f"(d[0]), "+f"(d[1]), "+f"(d[2]), "+f"(d[3])
        : "r"(a0), "r"(a1), "r"(a2), "r"(a3), "r"(b0), "r"(b1));
}

__global__ void __launch_bounds__(NT, 2)
logsparse_flash_tc7_kernel(const float* __restrict__ Q,
                           const float* __restrict__ K,
                           const float* __restrict__ V,
                           float* __restrict__ O) {
    extern __shared__ char smc[];
    uint2* KH = (uint2*)smc;                 // [64 key][KSu d]
    uint2* VH = KH + 64 * KSu;               // [64 key][KSu d]
    float* Pa = (float*)(VH + 64 * KSu);     // NW x [16][PSf]

    // Heavy blocks (large m) first: flatten triangular imbalance.
    const int m  = (int)gridDim.x - 1 - (int)blockIdx.x;
    const int bh = blockIdx.y;
    const int b  = bh >> 4;
    const int h  = bh & 15;

    const int tid  = threadIdx.x;
    const int wid  = tid >> 5;
    const int lane = tid & 31;
    const int g    = lane >> 2;
    const int tg   = lane & 3;

    float* Pw = Pa + wid * (16 * PSf);
    const int R0      = wid * 16;
    const int gRowA   = m * BM + R0 + g;
    const int gRowB   = gRowA + 8;
    const int wRowMax = m * BM + R0 + 15;    // LANE-UNIFORM warp row bound

    const size_t rs = (size_t)Hc * Dc;       // 1024 floats between seq positions
    const float* Qg = Q + ((size_t)b * Lc + (size_t)m * BM) * rs + (size_t)h * Dc;
    const float* Kg = K + (size_t)b * Lc * rs + (size_t)h * Dc;
    const float* Vg = V + (size_t)b * Lc * rs + (size_t)h * Dc;

    // ---- Q fragments once, pre-scaled by log2(e) (exp -> exp2) ----
    const float LOG2E = 1.4426950408889634f;
    float qf[8][4];
#pragma unroll
    for (int cc = 0; cc < 8; ++cc) {
        int k0 = 8 * cc + tg;
        qf[cc][0] = Qg[(size_t)(R0 + g)     * rs + k0]     * LOG2E;
        qf[cc][1] = Qg[(size_t)(R0 + g + 8) * rs + k0]     * LOG2E;
        qf[cc][2] = Qg[(size_t)(R0 + g)     * rs + k0 + 4] * LOG2E;
        qf[cc][3] = Qg[(size_t)(R0 + g + 8) * rs + k0 + 4] * LOG2E;
    }

    // ---- State (log2 domain) + O accumulators ----
    float o[8][4];
    float mA = -1e30f, mB = -1e30f, lA = 0.f, lB = 0.f;
#pragma unroll
    for (int j = 0; j < 8; ++j) { o[j][0] = o[j][1] = o[j][2] = o[j][3] = 0.f; }

    const int nend = (m * BM + BM - 1) / BN;    // 2m+1

    for (int n = 0; n <= nend; ++n) {
        __syncthreads();
        const int nBase = n * BN;
        // ---- Load K,V tile; split to tf32 hi/lo once ----
#pragma unroll
        for (int it = 0; it < 4; ++it) {
            int idx = tid + it * NT;       // 0..1023
            int r = idx >> 4, c4 = idx & 15;
            const size_t go = (size_t)(nBase + r) * rs + c4 * 4;
            float4 kv = *(const float4*)(Kg + go);
            float4 vv = *(const float4*)(Vg + go);
            uint2* kd = KH + r * KSu + c4 * 4;
            uint2* vd = VH + r * KSu + c4 * 4;
            uint32_t hi, lo;
            tf32_split(kv.x, hi, lo); kd[0] = make_uint2(hi, lo);
            tf32_split(kv.y, hi, lo); kd[1] = make_uint2(hi, lo);
            tf32_split(kv.z, hi, lo); kd[2] = make_uint2(hi, lo);
            tf32_split(kv.w, hi, lo); kd[3] = make_uint2(hi, lo);
            tf32_split(vv.x, hi, lo); vd[0] = make_uint2(hi, lo);
            tf32_split(vv.y, hi, lo); vd[1] = make_uint2(hi, lo);
            tf32_split(vv.z, hi, lo); vd[2] = make_uint2(hi, lo);
            tf32_split(vv.w, hi, lo); vd[3] = make_uint2(hi, lo);
        }
        __syncthreads();

        if (nBase > wRowMax) continue;     // warp fully masked (uniform)

        // ---- S = Q K^T via 3xTF32 mma ----
        float s[8][4];
#pragma unroll
        for (int j = 0; j < 8; ++j) { s[j][0] = s[j][1] = s[j][2] = s[j][3] = 0.f; }

#pragma unroll
        for (int cc = 0; cc < 8; ++cc) {
            uint32_t qh[4], ql[4];
#pragma unroll
            for (int e = 0; e < 4; ++e) tf32_split(qf[cc][e], qh[e], ql[e]);
#pragma unroll
            for (int j = 0; j < 8; ++j) {
                uint2 k0 = KH[(8 * j + g) * KSu + 8 * cc + tg];
                uint2 k1 = KH[(8 * j + g) * KSu + 8 * cc + tg + 4];
                mma8(s[j], qh[0], qh[1], qh[2], qh[3], k0.x, k1.x);
                mma8(s[j], ql[0], ql[1], ql[2], ql[3], k0.x, k1.x);
                mma8(s[j], qh[0], qh[1], qh[2], qh[3], k0.y, k1.y);
            }
        }

        // ---- Causal mask (only blocks touching the diagonal) ----
        if (nBase + BN - 1 > m * BM + R0) {
#pragma unroll
            for (int j = 0; j < 8; ++j) {
                int c0 = nBase + 8 * j + 2 * tg;
                if (c0     > gRowA) s[j][0] = -1e30f;
                if (c0 + 1 > gRowA) s[j][1] = -1e30f;
                if (c0     > gRowB) s[j][2] = -1e30f;
                if (c0 + 1 > gRowB) s[j][3] = -1e30f;
            }
        }

        // ---- Online softmax (log2 domain), stage tf32-rounded P ----
        float tA = s[0][0], tB = s[0][2];
#pragma unroll
        for (int j = 0; j < 8; ++j) {
            tA = fmaxf(tA, fmaxf(s[j][0], s[j][1]));
            tB = fmaxf(tB, fmaxf(s[j][2], s[j][3]));
        }
        tA = fmaxf(tA, __shfl_xor_sync(0xffffffffu, tA, 1));
        tA = fmaxf(tA, __shfl_xor_sync(0xffffffffu, tA, 2));
        tB = fmaxf(tB, __shfl_xor_sync(0xffffffffu, tB, 1));
        tB = fmaxf(tB, __shfl_xor_sync(0xffffffffu, tB, 2));
        float mnA = fmaxf(mA, tA), mnB = fmaxf(mB, tB);
        float scA = exp2f(mA - mnA), scB = exp2f(mB - mnB);
        float rsA = 0.f, rsB = 0.f;
#pragma unroll
        for (int j = 0; j < 8; ++j) {
            // exp2, round to tf32 ONCE; rounded value feeds both the row-sum
            // and the PV mma, so normalization is self-consistent.
            uint32_t p0 = tf32_rna(exp2f(s[j][0] - mnA));
            uint32_t p1 = tf32_rna(exp2f(s[j][1] - mnA));
            uint32_t p2 = tf32_rna(exp2f(s[j][2] - mnB));
            uint32_t p3 = tf32_rna(exp2f(s[j][3] - mnB));
            rsA += __uint_as_float(p0) + __uint_as_float(p1);
            rsB += __uint_as_float(p2) + __uint_as_float(p3);
            int c = 8 * j + 2 * tg;
            *(float2*)(Pw + (g)     * PSf + c) =
                make_float2(__uint_as_float(p0), __uint_as_float(p1));
            *(float2*)(Pw + (g + 8) * PSf + c) =
                make_float2(__uint_as_float(p2), __uint_as_float(p3));
        }
        rsA += __shfl_xor_sync(0xffffffffu, rsA, 1);
        rsA += __shfl_xor_sync(0xffffffffu, rsA, 2);
        rsB += __shfl_xor_sync(0xffffffffu, rsB, 1);
        rsB += __shfl_xor_sync(0xffffffffu, rsB, 2);
        lA = lA * scA + rsA;  mA = mnA;
        lB = lB * scB + rsB;  mB = mnB;
#pragma unroll
        for (int j = 0; j < 8; ++j) {
            o[j][0] *= scA; o[j][1] *= scA;
            o[j][2] *= scB; o[j][3] *= scB;
        }
        __syncwarp();

        // ---- O += P V : 2 mma terms (P exact tf32, V hi+lo) ----
#pragma unroll
        for (int cc = 0; cc < 8; ++cc) {
            uint32_t a0 = __float_as_uint(Pw[(g)     * PSf + 8 * cc + tg]);
            uint32_t a1 = __float_as_uint(Pw[(g + 8) * PSf + 8 * cc + tg]);
            uint32_t a2 = __float_as_uint(Pw[(g)     * PSf + 8 * cc + tg + 4]);
            uint32_t a3 = __float_as_uint(Pw[(g + 8) * PSf + 8 * cc + tg + 4]);
#pragma unroll
            for (int j = 0; j < 8; ++j) {
                uint2 v0 = VH[(8 * cc + tg)     * KSu + 8 * j + g];
                uint2 v1 = VH[(8 * cc + tg + 4) * KSu + 8 * j + g];
                mma8(o[j], a0, a1, a2, a3, v0.x, v1.x);
                mma8(o[j], a0, a1, a2, a3, v0.y, v1.y);
            }
        }
    }

    // ---- Epilogue: normalize, store (output [B, H, L, D]) ----
    float* Og = O + ((size_t)(b * Hc + h) * Lc + (size_t)m * BM) * Dc;
    float invA = 1.f / lA, invB = 1.f / lB;
#pragma unroll
    for (int j = 0; j < 8; ++j) {
        int c = 8 * j + 2 * tg;
        *(float2*)(Og + (size_t)(R0 + g)     * Dc + c) = make_float2(o[j][0] * invA, o[j][1] * invA);
        *(float2*)(Og + (size_t)(R0 + g + 8) * Dc + c) = make_float2(o[j][2] * invB, o[j][3] * invB);
    }
}

extern "C" void kernel_launch(void* const* d_in, const int* in_sizes, int n_in,
                              void* d_out, int out_size) {
    const float* Q = (const float*)d_in[0];
    const float* K = (const float*)d_in[1];
    const float* V = (const float*)d_in[2];
    float* O = (float*)d_out;

    cudaFuncSetAttribute(logsparse_flash_tc7_kernel,
                         cudaFuncAttributeMaxDynamicSharedMemorySize, SMEM_BYTES);

    dim3 grid(Lc / BM, Bc * Hc);
    logsparse_flash_tc7_kernel<<<grid, NT, SMEM_BYTES>>>(Q, K, V, O);
}